// round 5
// baseline (speedup 1.0000x reference)
#include <cuda_runtime.h>

#define M_   64
#define L_   32
#define P_   100
#define NC_  400
#define NPAIR_ (NC_/2)
#define PTS_PER_BLK 3
#define ITEMS_PER_PT (NPAIR_ + 1)          // 200 C-pairs + 1 e00
#define TWO_PI_F 6.28318530717958647692f

typedef unsigned long long ull;

struct Layer { float d, inv_a, inv_b, b2, rho, inv_rho; };

__device__ Layer g_layers[M_ * L_];
__device__ float g_rng[M_ * P_];
__device__ float g_e00[M_ * P_];

// ---------------------------------------------------------------------------
// Packed fp32x2 helpers
// ---------------------------------------------------------------------------
struct F2 { ull v; };
__device__ __forceinline__ F2 f2pk(float a, float b) {
    F2 r; asm("mov.b64 %0,{%1,%2};" : "=l"(r.v) : "f"(a), "f"(b)); return r;
}
__device__ __forceinline__ void f2up(F2 a, float& x, float& y) {
    asm("mov.b64 {%0,%1},%2;" : "=f"(x), "=f"(y) : "l"(a.v));
}
__device__ __forceinline__ F2 f2mul(F2 a, F2 b) {
    F2 r; asm("mul.rn.f32x2 %0,%1,%2;" : "=l"(r.v) : "l"(a.v), "l"(b.v)); return r;
}
__device__ __forceinline__ F2 f2add(F2 a, F2 b) {
    F2 r; asm("add.rn.f32x2 %0,%1,%2;" : "=l"(r.v) : "l"(a.v), "l"(b.v)); return r;
}
__device__ __forceinline__ F2 f2sub(F2 a, F2 b) {
    F2 r; asm("sub.rn.f32x2 %0,%1,%2;" : "=l"(r.v) : "l"(a.v), "l"(b.v)); return r;
}
__device__ __forceinline__ F2 f2fma(F2 a, F2 b, F2 c) {
    F2 r; asm("fma.rn.f32x2 %0,%1,%2,%3;" : "=l"(r.v) : "l"(a.v), "l"(b.v), "l"(c.v)); return r;
}
__device__ __forceinline__ float frsqa(float x) {
    float r; asm("rsqrt.approx.f32 %0,%1;" : "=f"(r) : "f"(x)); return r;
}
__device__ __forceinline__ float fsqrta(float x) {
    float r; asm("sqrt.approx.f32 %0,%1;" : "=f"(r) : "f"(x)); return r;
}
__device__ __forceinline__ ull dupf(float f) {
    unsigned u = __float_as_uint(f); return ((ull)u << 32) | (ull)u;
}
// order-preserving float<->uint mapping
__device__ __forceinline__ unsigned ford(float f) {
    unsigned u = __float_as_uint(f);
    return (u & 0x80000000u) ? ~u : (u | 0x80000000u);
}
__device__ __forceinline__ float funord(unsigned u) {
    return (u & 0x80000000u) ? __uint_as_float(u & 0x7FFFFFFFu) : __uint_as_float(~u);
}

__device__ __forceinline__ void half_lane(
    float wv2, float xka2h, float xkb2h, float gmkh, float rhoh,
    float& e0, float& e1, float& e2, float& e3, float& e4)
{
    float ra = fsqrta(fabsf(wv2 - xka2h));
    float rb = fsqrta(fabsf(wv2 - xkb2h));
    float gam = gmkh * wv2, gamm1 = gam - 1.0f;
    float rarb = ra * rb;
    e0 = rhoh * rhoh * (gamm1 * gamm1 - gam * gmkh * rarb);
    e1 = -rhoh * ra;
    e2 = rhoh * (gamm1 - gmkh * rarb);
    e3 = rhoh * rb;
    e4 = wv2 - rarb;
}

// ---------------------------------------------------------------------------
__global__ void prepKernel(const float* __restrict__ d, const float* __restrict__ b) {
    int i = blockIdx.x * blockDim.x + threadIdx.x;
    if (i >= M_ * L_) return;
    float bb = b[i];
    float b2 = bb * bb, b3 = b2 * bb, b4 = b2 * b2;
    float a = 0.9409f + 2.0947f * bb - 0.8206f * b2 + 0.2683f * b3 - 0.0251f * b4;
    float a2 = a * a, a3 = a2 * a, a4 = a2 * a2, a5 = a4 * a;
    float rho = 1.6612f * a - 0.4721f * a2 + 0.0671f * a3 - 0.0043f * a4 + 0.000106f * a5;
    Layer ly;
    ly.d = d[i]; ly.inv_a = 1.0f / a; ly.inv_b = 1.0f / bb;
    ly.b2 = b2;  ly.rho = rho;        ly.inv_rho = 1.0f / rho;
    g_layers[i] = ly;
}

__global__ void dummyKernel() {}   // ncu capture alignment

// ---------------------------------------------------------------------------
// Det grid: PTS_PER_BLK points per block; uniform full-warp passes over items
// (lanes past the end recompute the last item, results discarded) so warp
// votes can use the full mask. Warp-uniform all-evanescent fast path skips
// sincos + selects entirely.
// ---------------------------------------------------------------------------
__global__ void __launch_bounds__(128, 7) detKernel(const float* __restrict__ tlist,
                                                    const float* __restrict__ Clist,
                                                    const float* __restrict__ vlist) {
    __shared__ float sD[PTS_PER_BLK * L_], sXka[PTS_PER_BLK * L_], sXka2[PTS_PER_BLK * L_];
    __shared__ float sXkb[PTS_PER_BLK * L_], sXkb2[PTS_PER_BLK * L_];
    __shared__ ull pGmk[PTS_PER_BLK * L_], pRho[PTS_PER_BLK * L_], pNRho[PTS_PER_BLK * L_],
                   pNRho2[PTS_PER_BLK * L_], pRhoI[PTS_PER_BLK * L_], pNRhoI[PTS_PER_BLK * L_],
                   pNRhoI2[PTS_PER_BLK * L_];
    __shared__ float sGmkH[PTS_PER_BLK], sRhoH[PTS_PER_BLK];
    __shared__ float sOmg[PTS_PER_BLK], sV[PTS_PER_BLK];
    __shared__ unsigned sMnU[PTS_PER_BLK], sMxU[PTS_PER_BLK];
    __shared__ float shC[NC_];

    int tid = threadIdx.x;
    int p0 = blockIdx.x * PTS_PER_BLK;
    int npts = min(PTS_PER_BLK, M_ * P_ - p0);

    if (tid < npts) {
        sOmg[tid] = TWO_PI_F / tlist[p0 + tid];
        sV[tid] = vlist[p0 + tid];
        sMnU[tid] = 0xFFFFFFFFu;
        sMxU[tid] = 0u;
    }
    for (int i = tid; i < npts * L_; i += 128) {
        int s = i >> 5, l = i & 31;
        int pt = p0 + s;
        float omega = fmaxf(TWO_PI_F / tlist[pt], 1e-4f);
        Layer ly = g_layers[(pt / P_) * L_ + l];
        float xka = omega * ly.inv_a, xkb = omega * ly.inv_b;
        float iw = __fdividef(1.0f, omega);
        float gmk = 2.0f * ly.b2 * iw * iw;
        sD[i] = ly.d; sXka[i] = xka; sXka2[i] = xka * xka;
        sXkb[i] = xkb; sXkb2[i] = xkb * xkb;
        pGmk[i]    = dupf(gmk);
        pRho[i]    = dupf(ly.rho);
        pNRho[i]   = dupf(-ly.rho);
        pNRho2[i]  = dupf(-ly.rho * ly.rho);
        pRhoI[i]   = dupf(ly.inv_rho);
        pNRhoI[i]  = dupf(-ly.inv_rho);
        pNRhoI2[i] = dupf(-ly.inv_rho * ly.inv_rho);
        if (l == L_ - 1) { sGmkH[s] = gmk; sRhoH[s] = ly.rho; }
    }
    for (int i = tid; i < NC_; i += 128) shC[i] = Clist[i];
    __syncthreads();

    int nit = npts * ITEMS_PER_PT;
    #pragma unroll 1
    for (int base = 0; base < nit; base += 128) {
        int it = base + tid;
        bool valid = it < nit;
        int itc = valid ? it : nit - 1;
        int j = (itc >= 2 * ITEMS_PER_PT) ? 2 : ((itc >= ITEMS_PER_PT) ? 1 : 0);
        int local = itc - j * ITEMS_PER_PT;
        int jo = j << 5;
        bool is_e00 = (local == NPAIR_);
        float omega_raw = sOmg[j];
        float den0 = is_e00 ? sV[j] : shC[2 * local];
        float den1 = is_e00 ? sV[j] : shC[2 * local + 1];
        float wv0 = __fdividef(omega_raw, den0);
        float wv1 = __fdividef(omega_raw, den1);
        float wv20 = wv0 * wv0, wv21 = wv1 * wv1;
        F2 W2 = f2pk(wv20, wv21);
        F2 Tp = f2pk(-2.0f * wv20, -2.0f * wv21);
        F2 ONE = f2pk(1.0f, 1.0f);

        float xka2_h = sXka2[jo + L_ - 1], xkb2_h = sXkb2[jo + L_ - 1];
        float gmk_h = sGmkH[j], rho_h = sRhoH[j];
        float h0a, h1a, h2a, h3a, h4a, h0b, h1b, h2b, h3b, h4b;
        half_lane(wv20, xka2_h, xkb2_h, gmk_h, rho_h, h0a, h1a, h2a, h3a, h4a);
        half_lane(wv21, xka2_h, xkb2_h, gmk_h, rho_h, h0b, h1b, h2b, h3b, h4b);
        F2 E0 = f2pk(h0a, h0b), E1 = f2pk(h1a, h1b), E2 = f2pk(h2a, h2b);
        F2 E3 = f2pk(h3a, h3b), E4 = f2pk(h4a, h4b);

        auto step = [&](int i, bool do_norm) {
            int li = jo + i;
            float dm = sD[li], xka = sXka[li], xka2 = sXka2[li], xkb = sXkb[li], xkb2 = sXkb2[li];

            // --- shared MUFU prelude (both paths) ---
            float ra20 = fabsf(wv20 - xka2), rb20 = fabsf(wv20 - xkb2);
            float ra21 = fabsf(wv21 - xka2), rb21 = fabsf(wv21 - xkb2);
            float ira0 = frsqa(ra20), irb0 = frsqa(rb20);
            float ira1 = frsqa(ra21), irb1 = frsqa(rb21);
            float ra0 = (ra20 > 0.0f) ? ra20 * ira0 : 0.0f;
            float rb0 = (rb20 > 0.0f) ? rb20 * irb0 : 0.0f;
            float ra1 = (ra21 > 0.0f) ? ra21 * ira1 : 0.0f;
            float rb1 = (rb21 > 0.0f) ? rb21 * irb1 : 0.0f;
            float pp0 = ra0 * dm, qq0 = rb0 * dm;
            float pp1 = ra1 * dm, qq1 = rb1 * dm;
            float ep0 = __expf(-pp0), eq0 = __expf(-qq0);
            float ep1 = __expf(-pp1), eq1 = __expf(-qq1);

            bool gt_a0 = wv0 > xka, gt_b0 = wv0 > xkb;
            bool gt_a1 = wv1 > xka, gt_b1 = wv1 > xkb;
            float cp0, cq0, w0, x0, y0, z0, a00;
            float cp1, cq1, w1, x1, y1, z1, a01;

            if (__all_sync(0xffffffffu, gt_a0 && gt_b0 && gt_a1 && gt_b1)) {
                // all-evanescent: no sincos, no selects
                float fp0 = ep0 * ep0, fq0 = eq0 * eq0;
                float fp1 = ep1 * ep1, fq1 = eq1 * eq1;
                cp0 = fmaf(0.5f, fp0, 0.5f); float sp0 = fmaf(-0.5f, fp0, 0.5f);
                cq0 = fmaf(0.5f, fq0, 0.5f); float sq0 = fmaf(-0.5f, fq0, 0.5f);
                cp1 = fmaf(0.5f, fp1, 0.5f); float sp1 = fmaf(-0.5f, fp1, 0.5f);
                cq1 = fmaf(0.5f, fq1, 0.5f); float sq1 = fmaf(-0.5f, fq1, 0.5f);
                w0 = sp0 * ira0; x0 = ra0 * sp0; y0 = sq0 * irb0; z0 = rb0 * sq0;
                w1 = sp1 * ira1; x1 = ra1 * sp1; y1 = sq1 * irb1; z1 = rb1 * sq1;
                a00 = ep0 * eq0;
                a01 = ep1 * eq1;
            } else {
                bool lt_a0 = wv0 < xka, lt_b0 = wv0 < xkb;
                bool lt_a1 = wv1 < xka, lt_b1 = wv1 < xkb;
                float sn, cs;
                __sincosf(pp0, &sn, &cs);
                {
                    float fp = ep0 * ep0;
                    float ce = fmaf(0.5f, fp, 0.5f), se = fmaf(-0.5f, fp, 0.5f);
                    cp0 = lt_a0 ? cs : ce;
                    w0 = lt_a0 ? sn * ira0 : (gt_a0 ? se * ira0 : dm);
                    x0 = lt_a0 ? -ra0 * sn : ra0 * se;
                }
                __sincosf(qq0, &sn, &cs);
                {
                    float fq = eq0 * eq0;
                    float ce = fmaf(0.5f, fq, 0.5f), se = fmaf(-0.5f, fq, 0.5f);
                    cq0 = lt_b0 ? cs : ce;
                    y0 = lt_b0 ? sn * irb0 : (gt_b0 ? se * irb0 : dm);
                    z0 = lt_b0 ? -rb0 * sn : rb0 * se;
                }
                __sincosf(pp1, &sn, &cs);
                {
                    float fp = ep1 * ep1;
                    float ce = fmaf(0.5f, fp, 0.5f), se = fmaf(-0.5f, fp, 0.5f);
                    cp1 = lt_a1 ? cs : ce;
                    w1 = lt_a1 ? sn * ira1 : (gt_a1 ? se * ira1 : dm);
                    x1 = lt_a1 ? -ra1 * sn : ra1 * se;
                }
                __sincosf(qq1, &sn, &cs);
                {
                    float fq = eq1 * eq1;
                    float ce = fmaf(0.5f, fq, 0.5f), se = fmaf(-0.5f, fq, 0.5f);
                    cq1 = lt_b1 ? cs : ce;
                    y1 = lt_b1 ? sn * irb1 : (gt_b1 ? se * irb1 : dm);
                    z1 = lt_b1 ? -rb1 * sn : rb1 * se;
                }
                a00 = (lt_a0 ? 1.0f : ep0) * (lt_b0 ? 1.0f : eq0);
                a01 = (lt_a1 ? 1.0f : ep1) * (lt_b1 ? 1.0f : eq1);
            }

            F2 Cp = f2pk(cp0, cp1), Cq = f2pk(cq0, cq1);
            F2 W = f2pk(w0, w1), X = f2pk(x0, x1), Y = f2pk(y0, y1), Z = f2pk(z0, z1);
            F2 A0 = f2pk(a00, a01);

            F2 Gmk;    Gmk.v    = pGmk[li];
            F2 Rho;    Rho.v    = pRho[li];
            F2 NRho;   NRho.v   = pNRho[li];
            F2 NRho2;  NRho2.v  = pNRho2[li];
            F2 RhoI;   RhoI.v   = pRhoI[li];
            F2 NRhoI;  NRhoI.v  = pNRhoI[li];
            F2 NRhoI2; NRhoI2.v = pNRhoI2[li];

            F2 Gam  = f2mul(Gmk, W2);
            F2 cpcq = f2mul(Cp, Cq);
            F2 cpy = f2mul(Cp, Y), cpz = f2mul(Cp, Z);
            F2 cqw = f2mul(Cq, W), cqx = f2mul(Cq, X);
            F2 xy = f2mul(X, Y), xz = f2mul(X, Z), wy = f2mul(W, Y), wz = f2mul(W, Z);
            F2 gamm1 = f2sub(Gam, ONE);
            F2 twgm1 = f2add(Gam, gamm1);
            F2 gmgmk = f2mul(Gam, Gmk);
            F2 gmgm1 = f2mul(Gam, gamm1);
            F2 gm1sq = f2mul(gamm1, gamm1);
            F2 a0pq  = f2sub(A0, cpcq);
            F2 A2    = f2add(a0pq, a0pq);
            F2 w2wy  = f2mul(W2, wy);

            F2 u = f2fma(gm1sq, w2wy, f2mul(gmgmk, xz));
            u = f2fma(gmgm1, A2, u);
            F2 c00 = f2sub(cpcq, u);
            F2 c01 = f2mul(f2sub(f2mul(W2, cpy), cqx), RhoI);
            F2 v = f2fma(Gmk, xz, f2mul(gamm1, w2wy));
            v = f2fma(twgm1, a0pq, v);
            F2 c02 = f2mul(v, NRhoI);
            F2 c03 = f2mul(f2sub(cpz, f2mul(W2, cqw)), RhoI);
            F2 s = f2fma(W2, A2, xz);
            s = f2fma(W2, w2wy, s);
            F2 c04 = f2mul(s, NRhoI2);
            F2 c10 = f2mul(f2sub(f2mul(gmgmk, cpz), f2mul(gm1sq, cqw)), Rho);
            F2 c12 = f2sub(f2mul(Gmk, cpz), f2mul(gamm1, cqw));
            F2 c30 = f2mul(f2sub(f2mul(gm1sq, cpy), f2mul(gmgmk, cqx)), Rho);
            F2 c32 = f2sub(f2mul(gamm1, cpy), f2mul(Gmk, cqx));
            F2 gg   = f2mul(gmgmk, gm1sq);
            F2 gmk2 = f2mul(gmgmk, gmgmk);
            F2 g1q  = f2mul(gm1sq, gm1sq);
            F2 hh = f2fma(gmk2, xz, f2mul(g1q, wy));
            hh = f2fma(gg, A2, hh);
            F2 c40 = f2mul(hh, NRho2);
            F2 k1 = f2mul(f2mul(Gmk, gamm1), twgm1);
            F2 k2 = f2mul(gmgmk, Gmk);
            F2 k3 = f2mul(gamm1, gm1sq);
            F2 v2 = f2fma(k2, xz, f2mul(k3, wy));
            v2 = f2fma(k1, a0pq, v2);
            F2 c42 = f2mul(v2, NRho);
            F2 c20 = f2mul(Tp, c42), c21 = f2mul(Tp, c32);
            F2 c23 = f2mul(Tp, c12), c24 = f2mul(Tp, c02);
            F2 dd = f2sub(cpcq, c00);
            F2 c22 = f2add(A0, f2add(dd, dd));

            F2 ee0 = f2fma(E0, c00, f2fma(E1, c10, f2fma(E2, c20, f2fma(E3, c30, f2mul(E4, c40)))));
            F2 ee1 = f2fma(E0, c01, f2fma(E1, cpcq, f2fma(E2, c21, f2sub(f2mul(E4, c30), f2mul(E3, xy)))));
            F2 ee2 = f2fma(E0, c02, f2fma(E1, c12, f2fma(E2, c22, f2fma(E3, c32, f2mul(E4, c42)))));
            F2 ee3 = f2fma(E0, c03, f2fma(E2, c23, f2fma(E3, cpcq, f2sub(f2mul(E4, c10), f2mul(E1, wz)))));
            F2 ee4 = f2fma(E0, c04, f2fma(E1, c03, f2fma(E2, c24, f2fma(E3, c01, f2mul(E4, c00)))));

            if (do_norm) {
                float g0, q0, g1, q1, g2, q2, g3, q3, g4, q4;
                f2up(ee0, g0, q0); f2up(ee1, g1, q1); f2up(ee2, g2, q2);
                f2up(ee3, g3, q3); f2up(ee4, g4, q4);
                float t1a = fmaxf(fmaxf(fabsf(g0), fabsf(g1)),
                                  fmaxf(fmaxf(fabsf(g2), fabsf(g3)), fabsf(g4)));
                float t1b = fmaxf(fmaxf(fabsf(q0), fabsf(q1)),
                                  fmaxf(fmaxf(fabsf(q2), fabsf(q3)), fabsf(q4)));
                t1a = fmaxf(t1a, 1e-30f);
                t1b = fmaxf(t1b, 1e-30f);
                F2 Ti = f2pk(__fdividef(1.0f, t1a), __fdividef(1.0f, t1b));
                E0 = f2mul(ee0, Ti); E1 = f2mul(ee1, Ti); E2 = f2mul(ee2, Ti);
                E3 = f2mul(ee3, Ti); E4 = f2mul(ee4, Ti);
            } else {
                E0 = ee0; E1 = ee1; E2 = ee2; E3 = ee3; E4 = ee4;
            }
        };

        #pragma unroll 1
        for (int i = L_ - 2; i >= 1; i -= 2) {
            step(i, false);
            step(i - 1, true);
        }
        step(0, true);

        float d0, d1;
        f2up(E0, d0, d1);
        if (valid) {
            if (is_e00) {
                g_e00[p0 + j] = d0;
            } else {
                float lo = fminf(d0, d1), hi = fmaxf(d0, d1);
                atomicMin(&sMnU[j], ford(lo));
                atomicMax(&sMxU[j], ford(hi));
            }
        }
    }
    __syncthreads();
    if (tid < npts) {
        g_rng[p0 + tid] = funord(sMxU[tid]) - funord(sMnU[tid]);
    }
}

// ---------------------------------------------------------------------------
__global__ void __launch_bounds__(128) finalKernel(const float* __restrict__ b,
                                                   float* __restrict__ out) {
    __shared__ float red[4];
    int m = blockIdx.x;
    float acc = 0.0f;
    for (int p = threadIdx.x; p < P_; p += blockDim.x) {
        int idx = m * P_ + p;
        float v = g_e00[idx] / g_rng[idx];
        float pw = __expf(-2.3025850929940457f * fabsf(v));   // 0.1^|v|
        acc += fabsf(pw - 1.0f);
    }
    acc *= (1.0f / (float)P_);
    for (int i = threadIdx.x; i < L_; i += blockDim.x) {
        float bi = b[m * L_ + i];
        float val;
        if (i == 0)            val = bi - b[m * L_ + 1];
        else if (i == L_ - 1)  val = bi - b[m * L_ + L_ - 2];
        else                   val = 2.0f * bi - b[m * L_ + i - 1] - b[m * L_ + i + 1];
        acc += fabsf(val) * (1.0f / (float)L_);
    }
    #pragma unroll
    for (int o = 16; o > 0; o >>= 1) acc += __shfl_xor_sync(0xffffffffu, acc, o);
    int wid = threadIdx.x >> 5;
    if ((threadIdx.x & 31) == 0) red[wid] = acc;
    __syncthreads();
    if (threadIdx.x == 0) out[m] = red[0] + red[1] + red[2] + red[3];
}

// ---------------------------------------------------------------------------
extern "C" void kernel_launch(void* const* d_in, const int* in_sizes, int n_in,
                              void* d_out, int out_size) {
    const float* vlist = (const float*)d_in[0];
    const float* tlist = (const float*)d_in[1];
    const float* d     = (const float*)d_in[2];
    const float* b     = (const float*)d_in[3];
    const float* Clist = (const float*)d_in[4];
    float* out = (float*)d_out;

    dummyKernel<<<1, 32>>>();
    dummyKernel<<<1, 32>>>();
    prepKernel<<<(M_ * L_ + 255) / 256, 256>>>(d, b);
    int nblk = (M_ * P_ + PTS_PER_BLK - 1) / PTS_PER_BLK;
    detKernel<<<nblk, 128>>>(tlist, Clist, vlist);
    dummyKernel<<<1, 32>>>();   // keeps launch positions stable for ncu -s
    finalKernel<<<M_, 128>>>(b, out);
}